// round 1
// baseline (speedup 1.0000x reference)
#include <cuda_runtime.h>

// EfficientPWL: out = (x - cp[ind2]) * slopes[c, ind1] + cumbias[c, ind2]
// with uniform breakpoints cpnts = linspace(-1, 1, 33), dt = 1/16.
//
// B=32, C=128, T=8192. One block per (b,c) row. Tables in shared memory.

#define BATCH   32
#define CCH     128
#define TLEN    8192
#define NCP     33      // number of breakpoints (cumbias entries)
#define NSL     34      // slopes per channel
#define THREADS 256

__device__ __forceinline__ float pwl_one(float xv,
                                         const float* __restrict__ s_slope,
                                         const float* __restrict__ s_cumb) {
    // ind1 = searchsorted(cpnts, x, side='right') on uniform grid
    float t = (xv + 1.0f) * 16.0f;
    int i1 = (int)floorf(t) + 1;
    i1 = max(0, min(NCP, i1));          // [0, 33]
    int i2 = max(i1 - 1, 0);            // [0, 32]
    float cp = -1.0f + 0.0625f * (float)i2;
    return (xv - cp) * s_slope[i1] + s_cumb[i2];
}

__global__ void __launch_bounds__(THREADS)
efficient_pwl_kernel(const float* __restrict__ x,
                     const float* __restrict__ slopes,
                     const float* __restrict__ biases,
                     float* __restrict__ out) {
    __shared__ float s_slope[NSL];
    __shared__ float s_cumb[NCP];

    const int row = blockIdx.x;          // b*C + c
    const int c   = row & (CCH - 1);
    const int tid = threadIdx.x;

    if (tid < NSL)
        s_slope[tid] = slopes[c * NSL + tid];
    __syncthreads();

    if (tid == 0) {
        const float dt = 0.0625f;
        float acc = biases[c];
        s_cumb[0] = acc;
        #pragma unroll
        for (int j = 1; j < NCP; j++) {
            acc = fmaf(s_slope[j], dt, acc);
            s_cumb[j] = acc;
        }
    }
    __syncthreads();

    const float4* __restrict__ xin = (const float4*)(x + (size_t)row * TLEN);
    float4* __restrict__ o         = (float4*)(out + (size_t)row * TLEN);

    // 2048 float4 per row / 256 threads = 8 iterations, fully unrolled for MLP
    #pragma unroll
    for (int i = 0; i < 8; i++) {
        const int idx = tid + i * THREADS;
        float4 v = xin[idx];
        float4 r;
        r.x = pwl_one(v.x, s_slope, s_cumb);
        r.y = pwl_one(v.y, s_slope, s_cumb);
        r.z = pwl_one(v.z, s_slope, s_cumb);
        r.w = pwl_one(v.w, s_slope, s_cumb);
        o[idx] = r;
    }
}

extern "C" void kernel_launch(void* const* d_in, const int* in_sizes, int n_in,
                              void* d_out, int out_size) {
    const float* x      = (const float*)d_in[0];
    const float* slopes = (const float*)d_in[1];
    const float* biases = (const float*)d_in[2];
    float* out          = (float*)d_out;

    const int rows = BATCH * CCH;  // 4096
    efficient_pwl_kernel<<<rows, THREADS>>>(x, slopes, biases, out);
}